// round 1
// baseline (speedup 1.0000x reference)
#include <cuda_runtime.h>

#define HW 90000
#define FULLM 0xffffffffu

// ---------------- scratch (device globals; no allocations allowed) ----------
__device__ float g_y1[HW * 64];     // conv1 raw output, pixel-major [p][64]
__device__ float g_xc[HW * 128];    // [p][0:64)=xa (attn branch), [p][64:128)=x1
__device__ float g_img[HW * 64];    // attention scattered image, pixel-major
__device__ float g_y2[HW * 64];     // conv2 raw output, pixel-major
__device__ float g_stats[256];      // sum1[64] sumsq1[64] sum2[64] sumsq2[64]
__device__ float g_bn[256];         // scale1 shift1 scale2 shift2

__global__ void k_zero() {
    g_stats[threadIdx.x] = 0.f;
}

// ---------------- conv1: y1[p][o] = sum_c w1[o][c] * x[c][p]  + BN stats ----
__global__ void __launch_bounds__(256) k_conv1(const float* __restrict__ x,
                                               const float* __restrict__ w) {
    __shared__ float s_w[2048];            // [kk(32)][o(64)]
    __shared__ float s_part[2][8][64];
    int tid = threadIdx.x;
    int p = blockIdx.x * 256 + tid;
    bool valid = p < HW;

    float acc[64];
#pragma unroll
    for (int c = 0; c < 64; c++) acc[c] = 0.f;

    for (int k0 = 0; k0 < 256; k0 += 32) {
        __syncthreads();
        for (int t = tid; t < 2048; t += 256) {
            int c = t & 63, kk = t >> 6;
            s_w[t] = w[c * 256 + k0 + kk];
        }
        __syncthreads();
#pragma unroll
        for (int kk = 0; kk < 32; kk++) {
            float xv = valid ? x[(k0 + kk) * HW + p] : 0.f;
            const float4* w4 = (const float4*)(s_w + kk * 64);
#pragma unroll
            for (int c4 = 0; c4 < 16; c4++) {
                float4 wv = w4[c4];
                acc[c4 * 4 + 0] = fmaf(wv.x, xv, acc[c4 * 4 + 0]);
                acc[c4 * 4 + 1] = fmaf(wv.y, xv, acc[c4 * 4 + 1]);
                acc[c4 * 4 + 2] = fmaf(wv.z, xv, acc[c4 * 4 + 2]);
                acc[c4 * 4 + 3] = fmaf(wv.w, xv, acc[c4 * 4 + 3]);
            }
        }
    }

    if (valid) {
        float4* o4 = (float4*)(g_y1 + (size_t)p * 64);
#pragma unroll
        for (int c4 = 0; c4 < 16; c4++)
            o4[c4] = make_float4(acc[c4 * 4], acc[c4 * 4 + 1], acc[c4 * 4 + 2], acc[c4 * 4 + 3]);
    }

    int lane = tid & 31, wrp = tid >> 5;
#pragma unroll
    for (int c = 0; c < 64; c++) {
        float v = valid ? acc[c] : 0.f;
        float v2 = v * v;
#pragma unroll
        for (int off = 16; off; off >>= 1) {
            v  += __shfl_xor_sync(FULLM, v,  off);
            v2 += __shfl_xor_sync(FULLM, v2, off);
        }
        if (lane == 0) { s_part[0][wrp][c] = v; s_part[1][wrp][c] = v2; }
    }
    __syncthreads();
    if (tid < 64) {
        float s = 0.f, s2 = 0.f;
#pragma unroll
        for (int wv = 0; wv < 8; wv++) { s += s_part[0][wv][tid]; s2 += s_part[1][wv][tid]; }
        atomicAdd(&g_stats[tid], s);
        atomicAdd(&g_stats[64 + tid], s2);
    }
}

// ---------------- BN finalize -----------------------------------------------
__global__ void k_fin(const float* __restrict__ g, const float* __restrict__ b, int which) {
    int c = threadIdx.x;
    if (c < 64) {
        const float inv = 1.f / (float)HW;
        float m   = g_stats[which * 128 + c] * inv;
        float var = g_stats[which * 128 + 64 + c] * inv - m * m;
        float rs  = rsqrtf(var + 1e-5f);
        float sc  = rs * g[c];
        g_bn[which * 128 + c]      = sc;
        g_bn[which * 128 + 64 + c] = b[c] - m * sc;
    }
}

// ---------------- apply BN1 + relu: y1 -> xc[:,64:128) ----------------------
__global__ void k_bnrelu1() {
    __shared__ float s_sc[64], s_sh[64];
    if (threadIdx.x < 64) {
        s_sc[threadIdx.x] = g_bn[threadIdx.x];
        s_sh[threadIdx.x] = g_bn[64 + threadIdx.x];
    }
    __syncthreads();
    int total = HW * 16;   // float4 count
    for (int idx = blockIdx.x * blockDim.x + threadIdx.x; idx < total;
         idx += gridDim.x * blockDim.x) {
        int p = idx >> 4, c4 = idx & 15;
        float4 v = ((const float4*)g_y1)[idx];
        int c = c4 * 4;
        v.x = fmaxf(fmaf(v.x, s_sc[c + 0], s_sh[c + 0]), 0.f);
        v.y = fmaxf(fmaf(v.y, s_sc[c + 1], s_sh[c + 1]), 0.f);
        v.z = fmaxf(fmaf(v.z, s_sc[c + 2], s_sh[c + 2]), 0.f);
        v.w = fmaxf(fmaf(v.w, s_sc[c + 3], s_sh[c + 3]), 0.f);
        ((float4*)g_xc)[p * 32 + 16 + c4] = v;
    }
}

// ---------------- attention: one CTA per (head, row-of-pos) -----------------
// tokens[b][j][d] = x1[h*32+d, pos[h,i,j]];  q,k,v in SMEM; softmax; out.
// Scatter: img[pix=pos[h,i,c]][h*32+e] = out[j][d] where j*32+d = e*300+c.
__global__ void __launch_bounds__(256) k_attn(const float* __restrict__ wq,
                                              const float* __restrict__ wkv,
                                              const int* __restrict__ obj_dict,
                                              const int* __restrict__ bg_dict,
                                              const int* __restrict__ rand_inds) {
    extern __shared__ float sm[];
    float* s_tok  = sm;                    // 300*33 (doubles as out)
    float* s_k    = s_tok  + 300 * 33;
    float* s_v    = s_k    + 300 * 33;
    float* s_wq   = s_v    + 300 * 33;     // 32*33
    float* s_wkv  = s_wq   + 32 * 33;      // 64*33
    float* s_dots = s_wkv  + 64 * 33;      // 8*304
    int*   s_pos  = (int*)(s_dots + 8 * 304);  // 300

    int b = blockIdx.x, h = b / 300, i = b % 300;
    int tid = threadIdx.x, lane = tid & 31, wrp = tid >> 5;

    for (int t = tid; t < 1024; t += 256) s_wq[(t >> 5) * 33 + (t & 31)] = wq[t];
    for (int t = tid; t < 2048; t += 256) s_wkv[(t >> 5) * 33 + (t & 31)] = wkv[t];
    const int* __restrict__ dict = (i < 150) ? obj_dict : bg_dict;
    for (int j = tid; j < 300; j += 256)
        s_pos[j] = dict[rand_inds[(h * 300 + i) * 300 + j]];
    __syncthreads();

    // gather tokens (coalesced 128B per row)
    for (int t = tid; t < 9600; t += 256) {
        int j = t >> 5, d = t & 31;
        s_tok[j * 33 + d] = g_xc[(size_t)s_pos[j] * 128 + 64 + h * 32 + d];
    }
    __syncthreads();

    // k, v projections (warp per row, lane = output channel)
    for (int j = wrp; j < 300; j += 8) {
        float aK = 0.f, aV = 0.f;
#pragma unroll
        for (int d = 0; d < 32; d++) {
            float t = s_tok[j * 33 + d];
            aK = fmaf(s_wkv[lane * 33 + d], t, aK);
            aV = fmaf(s_wkv[(32 + lane) * 33 + d], t, aV);
        }
        s_k[j * 33 + lane] = aK;
        s_v[j * 33 + lane] = aV;
    }
    __syncthreads();

    const float scale = 0.17677669529663687f;   // 32^-0.5
    for (int r = wrp; r < 300; r += 8) {
        // q row, then broadcast into registers
        float qv = 0.f;
#pragma unroll
        for (int d = 0; d < 32; d++) qv = fmaf(s_wq[lane * 33 + d], s_tok[r * 33 + d], qv);
        float qreg[32];
#pragma unroll
        for (int d = 0; d < 32; d++) qreg[d] = __shfl_sync(FULLM, qv, d);

        float dv[10];
        float mx = -1e30f;
#pragma unroll
        for (int t = 0; t < 10; t++) {
            int j = lane + t * 32;
            float s = -1e30f;
            if (j < 300) {
                float a = 0.f;
#pragma unroll
                for (int d = 0; d < 32; d++) a = fmaf(qreg[d], s_k[j * 33 + d], a);
                s = a * scale;
            }
            dv[t] = s;
            mx = fmaxf(mx, s);
        }
#pragma unroll
        for (int off = 16; off; off >>= 1) mx = fmaxf(mx, __shfl_xor_sync(FULLM, mx, off));

        float sum = 0.f;
#pragma unroll
        for (int t = 0; t < 10; t++) {
            int j = lane + t * 32;
            if (j < 300) {
                float e = __expf(dv[t] - mx);
                s_dots[wrp * 304 + j] = e;
                sum += e;
            }
        }
#pragma unroll
        for (int off = 16; off; off >>= 1) sum += __shfl_xor_sync(FULLM, sum, off);
        float invs = __frcp_rn(sum);

        // out row: lane = d
        float o = 0.f;
        for (int j = 0; j < 300; j++)
            o = fmaf(s_dots[wrp * 304 + j], s_v[j * 33 + lane], o);
        __syncwarp();
        s_tok[r * 33 + lane] = o * invs;   // row r owned by this warp only
    }
    __syncthreads();

    // scatter with the (j,d)->(e,c) reshape reinterpretation
    for (int t = tid; t < 9600; t += 256) {
        int c = t >> 5, e = t & 31;
        int idx = e * 300 + c;
        g_img[(size_t)s_pos[c] * 64 + h * 32 + e] = s_tok[(idx >> 5) * 33 + (idx & 31)];
    }
}

// ---------------- wo conv + bo + relu: img -> xc[:,0:64) --------------------
__global__ void __launch_bounds__(256) k_convwo(const float* __restrict__ wo,
                                                const float* __restrict__ bo) {
    __shared__ float s_w[4096];     // [c][o]
    __shared__ float s_in[256 * 9];
    __shared__ float s_bo[64];
    int tid = threadIdx.x;
    int p0 = blockIdx.x * 256, p = p0 + tid;
    bool valid = p < HW;

    for (int t = tid; t < 4096; t += 256) { int o = t & 63, c = t >> 6; s_w[t] = wo[o * 64 + c]; }
    if (tid < 64) s_bo[tid] = bo[tid];
    __syncthreads();

    float acc[64];
#pragma unroll
    for (int o = 0; o < 64; o++) acc[o] = s_bo[o];

    for (int c0 = 0; c0 < 64; c0 += 8) {
        __syncthreads();
        for (int t = tid; t < 2048; t += 256) {
            int pl = t >> 3, cc = t & 7;
            int pp = p0 + pl;
            s_in[pl * 9 + cc] = (pp < HW) ? g_img[(size_t)pp * 64 + c0 + cc] : 0.f;
        }
        __syncthreads();
#pragma unroll
        for (int cc = 0; cc < 8; cc++) {
            float xv = s_in[tid * 9 + cc];
            const float4* w4 = (const float4*)(s_w + (c0 + cc) * 64);
#pragma unroll
            for (int o4 = 0; o4 < 16; o4++) {
                float4 wv = w4[o4];
                acc[o4 * 4 + 0] = fmaf(wv.x, xv, acc[o4 * 4 + 0]);
                acc[o4 * 4 + 1] = fmaf(wv.y, xv, acc[o4 * 4 + 1]);
                acc[o4 * 4 + 2] = fmaf(wv.z, xv, acc[o4 * 4 + 2]);
                acc[o4 * 4 + 3] = fmaf(wv.w, xv, acc[o4 * 4 + 3]);
            }
        }
    }
    if (valid) {
        float4* o4p = (float4*)(g_xc + (size_t)p * 128);
#pragma unroll
        for (int o4 = 0; o4 < 16; o4++)
            o4p[o4] = make_float4(fmaxf(acc[o4 * 4], 0.f), fmaxf(acc[o4 * 4 + 1], 0.f),
                                  fmaxf(acc[o4 * 4 + 2], 0.f), fmaxf(acc[o4 * 4 + 3], 0.f));
    }
}

// ---------------- conv2 over concat [xa;x1] + BN2 stats ---------------------
__global__ void __launch_bounds__(256) k_conv2(const float* __restrict__ w2) {
    __shared__ float s_w[8192];     // [c(128)][o(64)]
    __shared__ float s_in[256 * 9];
    __shared__ float s_part[2][8][64];
    int tid = threadIdx.x;
    int p0 = blockIdx.x * 256, p = p0 + tid;
    bool valid = p < HW;

    for (int t = tid; t < 8192; t += 256) { int o = t & 63, c = t >> 6; s_w[t] = w2[o * 128 + c]; }

    float acc[64];
#pragma unroll
    for (int o = 0; o < 64; o++) acc[o] = 0.f;

    for (int c0 = 0; c0 < 128; c0 += 8) {
        __syncthreads();
        for (int t = tid; t < 2048; t += 256) {
            int pl = t >> 3, cc = t & 7;
            int pp = p0 + pl;
            s_in[pl * 9 + cc] = (pp < HW) ? g_xc[(size_t)pp * 128 + c0 + cc] : 0.f;
        }
        __syncthreads();
#pragma unroll
        for (int cc = 0; cc < 8; cc++) {
            float xv = s_in[tid * 9 + cc];
            const float4* w4 = (const float4*)(s_w + (c0 + cc) * 64);
#pragma unroll
            for (int o4 = 0; o4 < 16; o4++) {
                float4 wv = w4[o4];
                acc[o4 * 4 + 0] = fmaf(wv.x, xv, acc[o4 * 4 + 0]);
                acc[o4 * 4 + 1] = fmaf(wv.y, xv, acc[o4 * 4 + 1]);
                acc[o4 * 4 + 2] = fmaf(wv.z, xv, acc[o4 * 4 + 2]);
                acc[o4 * 4 + 3] = fmaf(wv.w, xv, acc[o4 * 4 + 3]);
            }
        }
    }

    if (valid) {
        float4* o4p = (float4*)(g_y2 + (size_t)p * 64);
#pragma unroll
        for (int o4 = 0; o4 < 16; o4++)
            o4p[o4] = make_float4(acc[o4 * 4], acc[o4 * 4 + 1], acc[o4 * 4 + 2], acc[o4 * 4 + 3]);
    }

    int lane = tid & 31, wrp = tid >> 5;
#pragma unroll
    for (int c = 0; c < 64; c++) {
        float v = valid ? acc[c] : 0.f;
        float v2 = v * v;
#pragma unroll
        for (int off = 16; off; off >>= 1) {
            v  += __shfl_xor_sync(FULLM, v,  off);
            v2 += __shfl_xor_sync(FULLM, v2, off);
        }
        if (lane == 0) { s_part[0][wrp][c] = v; s_part[1][wrp][c] = v2; }
    }
    __syncthreads();
    if (tid < 64) {
        float s = 0.f, s2 = 0.f;
#pragma unroll
        for (int wv = 0; wv < 8; wv++) { s += s_part[0][wv][tid]; s2 += s_part[1][wv][tid]; }
        atomicAdd(&g_stats[128 + tid], s);
        atomicAdd(&g_stats[192 + tid], s2);
    }
}

// ---------------- BN2 + relu, transpose to channel-major output -------------
__global__ void __launch_bounds__(256) k_out(float* __restrict__ out) {
    __shared__ float s[64 * 65];
    __shared__ float s_sc[64], s_sh[64];
    int tid = threadIdx.x;
    if (tid < 64) { s_sc[tid] = g_bn[128 + tid]; s_sh[tid] = g_bn[192 + tid]; }
    int p0 = blockIdx.x * 64;
    for (int t = tid; t < 4096; t += 256) {
        int pl = t >> 6, c = t & 63;
        int p = p0 + pl;
        s[pl * 65 + c] = (p < HW) ? g_y2[(size_t)p * 64 + c] : 0.f;
    }
    __syncthreads();
    for (int t = tid; t < 4096; t += 256) {
        int c = t >> 6, pl = t & 63;
        int p = p0 + pl;
        if (p < HW)
            out[(size_t)c * HW + p] = fmaxf(fmaf(s[pl * 65 + c], s_sc[c], s_sh[c]), 0.f);
    }
}

// ---------------- launch -----------------------------------------------------
extern "C" void kernel_launch(void* const* d_in, const int* in_sizes, int n_in,
                              void* d_out, int out_size) {
    const float* x   = (const float*)d_in[0];
    const float* w1  = (const float*)d_in[1];
    const float* g1  = (const float*)d_in[2];
    const float* b1  = (const float*)d_in[3];
    const float* wq  = (const float*)d_in[4];
    const float* wkv = (const float*)d_in[5];
    const float* wo  = (const float*)d_in[6];
    const float* bo  = (const float*)d_in[7];
    const float* w2  = (const float*)d_in[8];
    const float* g2  = (const float*)d_in[9];
    const float* b2  = (const float*)d_in[10];
    const int* objd  = (const int*)d_in[11];
    const int* bgd   = (const int*)d_in[12];
    const int* ri    = (const int*)d_in[13];
    float* out = (float*)d_out;

    k_zero<<<1, 256>>>();
    k_conv1<<<(HW + 255) / 256, 256>>>(x, w1);
    k_fin<<<1, 64>>>(g1, b1, 0);
    k_bnrelu1<<<1024, 256>>>();

    size_t smem = (size_t)(3 * 300 * 33 + 32 * 33 + 64 * 33 + 8 * 304) * sizeof(float)
                + 300 * sizeof(int);
    cudaFuncSetAttribute(k_attn, cudaFuncAttributeMaxDynamicSharedMemorySize, (int)smem);
    k_attn<<<600, 256, smem>>>(wq, wkv, objd, bgd, ri);

    k_convwo<<<(HW + 255) / 256, 256>>>(wo, bo);
    k_conv2<<<(HW + 255) / 256, 256>>>(w2);
    k_fin<<<1, 64>>>(g2, b2, 1);
    k_out<<<(HW + 63) / 64, 256>>>(out);
}

// round 3
// speedup vs baseline: 1.9143x; 1.9143x over previous
#include <cuda_runtime.h>
#include <cstdint>

#define HW 90000
#define FULLM 0xffffffffu

// ---------------- tf32 helpers ----------------------------------------------
__device__ __forceinline__ float tf32r(float x) {
    uint32_t u; asm("cvt.rna.tf32.f32 %0, %1;" : "=r"(u) : "f"(x));
    return __uint_as_float(u);
}
__device__ __forceinline__ void mma8(float c[4], float a0, float a1, float a2, float a3,
                                     float b0, float b1) {
    asm volatile("mma.sync.aligned.m16n8k8.row.col.f32.tf32.tf32.f32 "
        "{%0,%1,%2,%3}, {%4,%5,%6,%7}, {%8,%9}, {%0,%1,%2,%3};"
        : "+f"(c[0]), "+f"(c[1]), "+f"(c[2]), "+f"(c[3])
        : "r"(__float_as_uint(a0)), "r"(__float_as_uint(a1)),
          "r"(__float_as_uint(a2)), "r"(__float_as_uint(a3)),
          "r"(__float_as_uint(b0)), "r"(__float_as_uint(b1)));
}

// ---------------- scratch ----------------------------------------------------
__device__ float g_y1[HW * 64];
__device__ float g_xc[HW * 128];     // [p][0:64)=xa, [p][64:128)=x1
__device__ float g_img[HW * 64];
__device__ float g_y2[HW * 64];
__device__ float g_stats[256];
__device__ float g_bn[256];

__global__ void k_zero() { g_stats[threadIdx.x] = 0.f; }

// ---------------- conv1 + BN1 stats -----------------------------------------
__global__ void __launch_bounds__(256) k_conv1(const float* __restrict__ x,
                                               const float* __restrict__ w) {
    __shared__ float s_w[2048];
    __shared__ float s_part[2][8][64];
    int tid = threadIdx.x;
    int p = blockIdx.x * 256 + tid;
    bool valid = p < HW;
    float acc[64];
#pragma unroll
    for (int c = 0; c < 64; c++) acc[c] = 0.f;
    for (int k0 = 0; k0 < 256; k0 += 32) {
        __syncthreads();
        for (int t = tid; t < 2048; t += 256) {
            int c = t & 63, kk = t >> 6;
            s_w[t] = w[c * 256 + k0 + kk];
        }
        __syncthreads();
#pragma unroll
        for (int kk = 0; kk < 32; kk++) {
            float xv = valid ? x[(k0 + kk) * HW + p] : 0.f;
            const float4* w4 = (const float4*)(s_w + kk * 64);
#pragma unroll
            for (int c4 = 0; c4 < 16; c4++) {
                float4 wv = w4[c4];
                acc[c4 * 4 + 0] = fmaf(wv.x, xv, acc[c4 * 4 + 0]);
                acc[c4 * 4 + 1] = fmaf(wv.y, xv, acc[c4 * 4 + 1]);
                acc[c4 * 4 + 2] = fmaf(wv.z, xv, acc[c4 * 4 + 2]);
                acc[c4 * 4 + 3] = fmaf(wv.w, xv, acc[c4 * 4 + 3]);
            }
        }
    }
    if (valid) {
        float4* o4 = (float4*)(g_y1 + (size_t)p * 64);
#pragma unroll
        for (int c4 = 0; c4 < 16; c4++)
            o4[c4] = make_float4(acc[c4 * 4], acc[c4 * 4 + 1], acc[c4 * 4 + 2], acc[c4 * 4 + 3]);
    }
    int lane = tid & 31, wrp = tid >> 5;
#pragma unroll
    for (int c = 0; c < 64; c++) {
        float v = valid ? acc[c] : 0.f;
        float v2 = v * v;
#pragma unroll
        for (int off = 16; off; off >>= 1) {
            v  += __shfl_xor_sync(FULLM, v,  off);
            v2 += __shfl_xor_sync(FULLM, v2, off);
        }
        if (lane == 0) { s_part[0][wrp][c] = v; s_part[1][wrp][c] = v2; }
    }
    __syncthreads();
    if (tid < 64) {
        float s = 0.f, s2 = 0.f;
#pragma unroll
        for (int wv = 0; wv < 8; wv++) { s += s_part[0][wv][tid]; s2 += s_part[1][wv][tid]; }
        atomicAdd(&g_stats[tid], s);
        atomicAdd(&g_stats[64 + tid], s2);
    }
}

__global__ void k_fin(const float* __restrict__ g, const float* __restrict__ b, int which) {
    int c = threadIdx.x;
    if (c < 64) {
        const float inv = 1.f / (float)HW;
        float m   = g_stats[which * 128 + c] * inv;
        float var = g_stats[which * 128 + 64 + c] * inv - m * m;
        float rs  = rsqrtf(var + 1e-5f);
        float sc  = rs * g[c];
        g_bn[which * 128 + c]      = sc;
        g_bn[which * 128 + 64 + c] = b[c] - m * sc;
    }
}

__global__ void k_bnrelu1() {
    __shared__ float s_sc[64], s_sh[64];
    if (threadIdx.x < 64) {
        s_sc[threadIdx.x] = g_bn[threadIdx.x];
        s_sh[threadIdx.x] = g_bn[64 + threadIdx.x];
    }
    __syncthreads();
    int total = HW * 16;
    for (int idx = blockIdx.x * blockDim.x + threadIdx.x; idx < total;
         idx += gridDim.x * blockDim.x) {
        int p = idx >> 4, c4 = idx & 15;
        float4 v = ((const float4*)g_y1)[idx];
        int c = c4 * 4;
        v.x = fmaxf(fmaf(v.x, s_sc[c + 0], s_sh[c + 0]), 0.f);
        v.y = fmaxf(fmaf(v.y, s_sc[c + 1], s_sh[c + 1]), 0.f);
        v.z = fmaxf(fmaf(v.z, s_sc[c + 2], s_sh[c + 2]), 0.f);
        v.w = fmaxf(fmaf(v.w, s_sc[c + 3], s_sh[c + 3]), 0.f);
        ((float4*)g_xc)[p * 32 + 16 + c4] = v;
    }
}

// ---------------- fused attention: gather+proj+flash-mma+scatter ------------
// smem float offsets
#define WT_OFF   0                       // 32 x 97
#define TOK_OFF  3104                    // 304 x 36  (tokens -> Q -> O)
#define SK_OFF   (3104 + 10944)          // 320 x 36  (K, rows>=300 zero)
#define SV_OFF   (14048 + 11520)         // 320 x 40  (V, rows>=300 zero)
#define SP_OFF   (25568 + 12800)         // 8 warps x 16 x 68 (P chunks)
#define SPOS_OFF (38368 + 8704)          // 304 ints
#define ATTN_SMEM_F (47072 + 304)        // 47376 floats = 189504 B

__global__ void __launch_bounds__(256) k_attn(const float* __restrict__ wq,
                                              const float* __restrict__ wkv,
                                              const int* __restrict__ obj_dict,
                                              const int* __restrict__ bg_dict,
                                              const int* __restrict__ rand_inds) {
    extern __shared__ float sm[];
    float* s_wT  = sm + WT_OFF;
    float* s_tok = sm + TOK_OFF;
    float* s_k   = sm + SK_OFF;
    float* s_v   = sm + SV_OFF;
    float* s_p   = sm + SP_OFF;
    int*   s_pos = (int*)(sm + SPOS_OFF);

    int b = blockIdx.x, h = b / 300, i = b % 300;
    int tid = threadIdx.x, lane = tid & 31, wrp = tid >> 5;
    int g = lane >> 2, t = lane & 3;

    // weights transposed: s_wT[d][o], o: 0..31 q, 32..63 k, 64..95 v
    for (int idx = tid; idx < 1024; idx += 256) {
        int o = idx >> 5, d = idx & 31;
        s_wT[d * 97 + o] = wq[idx];
    }
    for (int idx = tid; idx < 2048; idx += 256) {
        int o = idx >> 5, d = idx & 31;
        s_wT[d * 97 + 32 + o] = wkv[idx];
    }
    const int* __restrict__ dict = (i < 150) ? obj_dict : bg_dict;
    for (int j = tid; j < 300; j += 256)
        s_pos[j] = dict[rand_inds[(h * 300 + i) * 300 + j]];
    // zero pad rows
    for (int idx = tid; idx < 4 * 36; idx += 256)  s_tok[300 * 36 + idx] = 0.f;
    for (int idx = tid; idx < 16 * 36; idx += 256) s_k[304 * 36 + idx]   = 0.f;
    for (int idx = tid; idx < 16 * 40; idx += 256) s_v[304 * 40 + idx]   = 0.f;
    __syncthreads();

    // gather tokens (coalesced 128B per row)
    for (int tt = tid; tt < 9600; tt += 256) {
        int j = tt >> 5, d = tt & 31;
        s_tok[j * 36 + d] = g_xc[(size_t)s_pos[j] * 128 + 64 + h * 32 + d];
    }
    __syncthreads();

    // Q/K/V projection; Q pre-scaled; all tf32-rounded. Q overwrites tok.
    const float qscale = 0.17677669529663687f;
    for (int j = wrp; j < 304; j += 8) {
        float aq = 0.f, ak = 0.f, av = 0.f;
#pragma unroll
        for (int d2 = 0; d2 < 32; d2++) {
            float tv = s_tok[j * 36 + d2];
            aq = fmaf(s_wT[d2 * 97 + lane], tv, aq);
            ak = fmaf(s_wT[d2 * 97 + 32 + lane], tv, ak);
            av = fmaf(s_wT[d2 * 97 + 64 + lane], tv, av);
        }
        s_k[j * 36 + lane] = tf32r(ak);
        s_v[j * 40 + lane] = tf32r(av);
        s_tok[j * 36 + lane] = tf32r(aq * qscale);
    }
    __syncthreads();

    // flash attention: warp owns 16-row M-tiles; 5 chunks of 64 cols (320, pad masked)
    float* pw = s_p + wrp * (16 * 68);
    for (int mt = wrp; mt < 19; mt += 8) {
        int m0 = mt * 16;
        float o[4][4];
#pragma unroll
        for (int a = 0; a < 4; a++)
#pragma unroll
            for (int bb = 0; bb < 4; bb++) o[a][bb] = 0.f;
        float mr0 = -1e30f, mr1 = -1e30f, l0 = 0.f, l1 = 0.f;

#pragma unroll 1
        for (int nc = 0; nc < 5; nc++) {
            int n0 = nc * 64;
            float cs[8][4];
#pragma unroll
            for (int nt = 0; nt < 8; nt++)
#pragma unroll
                for (int cc = 0; cc < 4; cc++) cs[nt][cc] = 0.f;
#pragma unroll
            for (int ks = 0; ks < 4; ks++) {
                int kc = ks * 8;
                float a0 = s_tok[(m0 + g) * 36 + kc + t];
                float a1 = s_tok[(m0 + g + 8) * 36 + kc + t];
                float a2 = s_tok[(m0 + g) * 36 + kc + t + 4];
                float a3 = s_tok[(m0 + g + 8) * 36 + kc + t + 4];
#pragma unroll
                for (int nt = 0; nt < 8; nt++) {
                    int nn = n0 + nt * 8 + g;
                    float b0 = s_k[nn * 36 + kc + t];
                    float b1 = s_k[nn * 36 + kc + t + 4];
                    mma8(cs[nt], a0, a1, a2, a3, b0, b1);
                }
            }
            if (nc == 4) {
#pragma unroll
                for (int nt = 0; nt < 8; nt++) {
                    int cg = 256 + nt * 8 + 2 * t;
                    if (cg >= 300)     { cs[nt][0] = -1e30f; cs[nt][2] = -1e30f; }
                    if (cg + 1 >= 300) { cs[nt][1] = -1e30f; cs[nt][3] = -1e30f; }
                }
            }
            // online softmax (rows g and g+8; quad = lanes sharing g)
            float cm0 = -1e30f, cm1 = -1e30f;
#pragma unroll
            for (int nt = 0; nt < 8; nt++) {
                cm0 = fmaxf(cm0, fmaxf(cs[nt][0], cs[nt][1]));
                cm1 = fmaxf(cm1, fmaxf(cs[nt][2], cs[nt][3]));
            }
            cm0 = fmaxf(cm0, __shfl_xor_sync(FULLM, cm0, 1));
            cm0 = fmaxf(cm0, __shfl_xor_sync(FULLM, cm0, 2));
            cm1 = fmaxf(cm1, __shfl_xor_sync(FULLM, cm1, 1));
            cm1 = fmaxf(cm1, __shfl_xor_sync(FULLM, cm1, 2));
            float nm0 = fmaxf(mr0, cm0), nm1 = fmaxf(mr1, cm1);
            float f0 = __expf(mr0 - nm0), f1 = __expf(mr1 - nm1);
            mr0 = nm0; mr1 = nm1;
            float sum0 = 0.f, sum1 = 0.f;
#pragma unroll
            for (int nt = 0; nt < 8; nt++) {
                float p0 = __expf(cs[nt][0] - nm0);
                float p1 = __expf(cs[nt][1] - nm0);
                float p2 = __expf(cs[nt][2] - nm1);
                float p3 = __expf(cs[nt][3] - nm1);
                sum0 += p0 + p1; sum1 += p2 + p3;
                int pc = nt * 8 + 2 * t;
                pw[g * 68 + pc]           = tf32r(p0);
                pw[g * 68 + pc + 1]       = tf32r(p1);
                pw[(g + 8) * 68 + pc]     = tf32r(p2);
                pw[(g + 8) * 68 + pc + 1] = tf32r(p3);
            }
            sum0 += __shfl_xor_sync(FULLM, sum0, 1);
            sum0 += __shfl_xor_sync(FULLM, sum0, 2);
            sum1 += __shfl_xor_sync(FULLM, sum1, 1);
            sum1 += __shfl_xor_sync(FULLM, sum1, 2);
            l0 = l0 * f0 + sum0;
            l1 = l1 * f1 + sum1;
#pragma unroll
            for (int ot = 0; ot < 4; ot++) {
                o[ot][0] *= f0; o[ot][1] *= f0;
                o[ot][2] *= f1; o[ot][3] *= f1;
            }
            __syncwarp();
            // O += P_chunk @ V_chunk
#pragma unroll
            for (int ks2 = 0; ks2 < 8; ks2++) {
                int kc = ks2 * 8;
                float a0 = pw[g * 68 + kc + t];
                float a1 = pw[(g + 8) * 68 + kc + t];
                float a2 = pw[g * 68 + kc + t + 4];
                float a3 = pw[(g + 8) * 68 + kc + t + 4];
                int kg = n0 + kc;
#pragma unroll
                for (int ot = 0; ot < 4; ot++) {
                    float b0 = s_v[(kg + t) * 40 + ot * 8 + g];
                    float b1 = s_v[(kg + t + 4) * 40 + ot * 8 + g];
                    mma8(o[ot], a0, a1, a2, a3, b0, b1);
                }
            }
            __syncwarp();
        }
        float i0 = __frcp_rn(l0), i1 = __frcp_rn(l1);
#pragma unroll
        for (int ot = 0; ot < 4; ot++) {
            int col = ot * 8 + 2 * t;
            s_tok[(m0 + g) * 36 + col]         = o[ot][0] * i0;
            s_tok[(m0 + g) * 36 + col + 1]     = o[ot][1] * i0;
            s_tok[(m0 + g + 8) * 36 + col]     = o[ot][2] * i1;
            s_tok[(m0 + g + 8) * 36 + col + 1] = o[ot][3] * i1;
        }
    }
    __syncthreads();

    // scatter with (j,d)->(e,c) reshape; coalesced on g_img
    for (int tt = tid; tt < 9600; tt += 256) {
        int c = tt >> 5, e = tt & 31;
        int idx = e * 300 + c;
        g_img[(size_t)s_pos[c] * 64 + h * 32 + e] = s_tok[(idx >> 5) * 36 + (idx & 31)];
    }
}

// ---------------- wo conv + bo + relu ---------------------------------------
__global__ void __launch_bounds__(256) k_convwo(const float* __restrict__ wo,
                                                const float* __restrict__ bo) {
    __shared__ float s_w[4096];
    __shared__ float s_in[256 * 9];
    __shared__ float s_bo[64];
    int tid = threadIdx.x;
    int p0 = blockIdx.x * 256, p = p0 + tid;
    bool valid = p < HW;
    for (int t = tid; t < 4096; t += 256) { int o = t & 63, c = t >> 6; s_w[t] = wo[o * 64 + c]; }
    if (tid < 64) s_bo[tid] = bo[tid];
    __syncthreads();
    float acc[64];
#pragma unroll
    for (int o = 0; o < 64; o++) acc[o] = s_bo[o];
    for (int c0 = 0; c0 < 64; c0 += 8) {
        __syncthreads();
        for (int t = tid; t < 2048; t += 256) {
            int pl = t >> 3, cc = t & 7;
            int pp = p0 + pl;
            s_in[pl * 9 + cc] = (pp < HW) ? g_img[(size_t)pp * 64 + c0 + cc] : 0.f;
        }
        __syncthreads();
#pragma unroll
        for (int cc = 0; cc < 8; cc++) {
            float xv = s_in[tid * 9 + cc];
            const float4* w4 = (const float4*)(s_w + (c0 + cc) * 64);
#pragma unroll
            for (int o4 = 0; o4 < 16; o4++) {
                float4 wv = w4[o4];
                acc[o4 * 4 + 0] = fmaf(wv.x, xv, acc[o4 * 4 + 0]);
                acc[o4 * 4 + 1] = fmaf(wv.y, xv, acc[o4 * 4 + 1]);
                acc[o4 * 4 + 2] = fmaf(wv.z, xv, acc[o4 * 4 + 2]);
                acc[o4 * 4 + 3] = fmaf(wv.w, xv, acc[o4 * 4 + 3]);
            }
        }
    }
    if (valid) {
        float4* o4p = (float4*)(g_xc + (size_t)p * 128);
#pragma unroll
        for (int o4 = 0; o4 < 16; o4++)
            o4p[o4] = make_float4(fmaxf(acc[o4 * 4], 0.f), fmaxf(acc[o4 * 4 + 1], 0.f),
                                  fmaxf(acc[o4 * 4 + 2], 0.f), fmaxf(acc[o4 * 4 + 3], 0.f));
    }
}

// ---------------- conv2 + BN2 stats -----------------------------------------
__global__ void __launch_bounds__(256) k_conv2(const float* __restrict__ w2) {
    __shared__ float s_w[8192];
    __shared__ float s_in[256 * 9];
    __shared__ float s_part[2][8][64];
    int tid = threadIdx.x;
    int p0 = blockIdx.x * 256, p = p0 + tid;
    bool valid = p < HW;
    for (int t = tid; t < 8192; t += 256) { int o = t & 63, c = t >> 6; s_w[t] = w2[o * 128 + c]; }
    float acc[64];
#pragma unroll
    for (int o = 0; o < 64; o++) acc[o] = 0.f;
    for (int c0 = 0; c0 < 128; c0 += 8) {
        __syncthreads();
        for (int t = tid; t < 2048; t += 256) {
            int pl = t >> 3, cc = t & 7;
            int pp = p0 + pl;
            s_in[pl * 9 + cc] = (pp < HW) ? g_xc[(size_t)pp * 128 + c0 + cc] : 0.f;
        }
        __syncthreads();
#pragma unroll
        for (int cc = 0; cc < 8; cc++) {
            float xv = s_in[tid * 9 + cc];
            const float4* w4 = (const float4*)(s_w + (c0 + cc) * 64);
#pragma unroll
            for (int o4 = 0; o4 < 16; o4++) {
                float4 wv = w4[o4];
                acc[o4 * 4 + 0] = fmaf(wv.x, xv, acc[o4 * 4 + 0]);
                acc[o4 * 4 + 1] = fmaf(wv.y, xv, acc[o4 * 4 + 1]);
                acc[o4 * 4 + 2] = fmaf(wv.z, xv, acc[o4 * 4 + 2]);
                acc[o4 * 4 + 3] = fmaf(wv.w, xv, acc[o4 * 4 + 3]);
            }
        }
    }
    if (valid) {
        float4* o4p = (float4*)(g_y2 + (size_t)p * 64);
#pragma unroll
        for (int o4 = 0; o4 < 16; o4++)
            o4p[o4] = make_float4(acc[o4 * 4], acc[o4 * 4 + 1], acc[o4 * 4 + 2], acc[o4 * 4 + 3]);
    }
    int lane = tid & 31, wrp = tid >> 5;
#pragma unroll
    for (int c = 0; c < 64; c++) {
        float v = valid ? acc[c] : 0.f;
        float v2 = v * v;
#pragma unroll
        for (int off = 16; off; off >>= 1) {
            v  += __shfl_xor_sync(FULLM, v,  off);
            v2 += __shfl_xor_sync(FULLM, v2, off);
        }
        if (lane == 0) { s_part[0][wrp][c] = v; s_part[1][wrp][c] = v2; }
    }
    __syncthreads();
    if (tid < 64) {
        float s = 0.f, s2 = 0.f;
#pragma unroll
        for (int wv = 0; wv < 8; wv++) { s += s_part[0][wv][tid]; s2 += s_part[1][wv][tid]; }
        atomicAdd(&g_stats[128 + tid], s);
        atomicAdd(&g_stats[192 + tid], s2);
    }
}

// ---------------- BN2 + relu + transpose to output --------------------------
__global__ void __launch_bounds__(256) k_out(float* __restrict__ out) {
    __shared__ float s[64 * 65];
    __shared__ float s_sc[64], s_sh[64];
    int tid = threadIdx.x;
    if (tid < 64) { s_sc[tid] = g_bn[128 + tid]; s_sh[tid] = g_bn[192 + tid]; }
    int p0 = blockIdx.x * 64;
    for (int t = tid; t < 4096; t += 256) {
        int pl = t >> 6, c = t & 63;
        int p = p0 + pl;
        s[pl * 65 + c] = (p < HW) ? g_y2[(size_t)p * 64 + c] : 0.f;
    }
    __syncthreads();
    for (int t = tid; t < 4096; t += 256) {
        int c = t >> 6, pl = t & 63;
        int p = p0 + pl;
        if (p < HW)
            out[(size_t)c * HW + p] = fmaxf(fmaf(s[pl * 65 + c], s_sc[c], s_sh[c]), 0.f);
    }
}

// ---------------- launch -----------------------------------------------------
extern "C" void kernel_launch(void* const* d_in, const int* in_sizes, int n_in,
                              void* d_out, int out_size) {
    const float* x   = (const float*)d_in[0];
    const float* w1  = (const float*)d_in[1];
    const float* g1  = (const float*)d_in[2];
    const float* b1  = (const float*)d_in[3];
    const float* wq  = (const float*)d_in[4];
    const float* wkv = (const float*)d_in[5];
    const float* wo  = (const float*)d_in[6];
    const float* bo  = (const float*)d_in[7];
    const float* w2  = (const float*)d_in[8];
    const float* g2  = (const float*)d_in[9];
    const float* b2  = (const float*)d_in[10];
    const int* objd  = (const int*)d_in[11];
    const int* bgd   = (const int*)d_in[12];
    const int* ri    = (const int*)d_in[13];
    float* out = (float*)d_out;

    k_zero<<<1, 256>>>();
    k_conv1<<<(HW + 255) / 256, 256>>>(x, w1);
    k_fin<<<1, 64>>>(g1, b1, 0);
    k_bnrelu1<<<1024, 256>>>();

    size_t attn_smem = (size_t)ATTN_SMEM_F * sizeof(float);
    cudaFuncSetAttribute(k_attn, cudaFuncAttributeMaxDynamicSharedMemorySize, (int)attn_smem);
    k_attn<<<600, 256, attn_smem>>>(wq, wkv, objd, bgd, ri);

    k_convwo<<<(HW + 255) / 256, 256>>>(wo, bo);
    k_conv2<<<(HW + 255) / 256, 256>>>(w2);
    k_fin<<<1, 64>>>(g2, b2, 1);
    k_out<<<(HW + 63) / 64, 256>>>(out);
}

// round 4
// speedup vs baseline: 2.3339x; 1.2191x over previous
#include <cuda_runtime.h>
#include <cstdint>

#define HW 90000
#define FULLM 0xffffffffu

// ---------------- tf32 helpers ----------------------------------------------
__device__ __forceinline__ float tf32r(float x) {
    uint32_t u; asm("cvt.rna.tf32.f32 %0, %1;" : "=r"(u) : "f"(x));
    return __uint_as_float(u);
}
__device__ __forceinline__ void mma8(float c[4], float a0, float a1, float a2, float a3,
                                     float b0, float b1) {
    asm volatile("mma.sync.aligned.m16n8k8.row.col.f32.tf32.tf32.f32 "
        "{%0,%1,%2,%3}, {%4,%5,%6,%7}, {%8,%9}, {%0,%1,%2,%3};"
        : "+f"(c[0]), "+f"(c[1]), "+f"(c[2]), "+f"(c[3])
        : "r"(__float_as_uint(a0)), "r"(__float_as_uint(a1)),
          "r"(__float_as_uint(a2)), "r"(__float_as_uint(a3)),
          "r"(__float_as_uint(b0)), "r"(__float_as_uint(b1)));
}

// ---------------- scratch ----------------------------------------------------
__device__ float g_y1[HW * 64];
__device__ float g_xc[HW * 128];     // [p][0:64)=xa, [p][64:128)=x1
__device__ float g_img[HW * 64];
__device__ float g_y2[HW * 64];
__device__ float g_stats[256];
__device__ float g_bn[256];

__global__ void k_zero() { g_stats[threadIdx.x] = 0.f; }

// ============================================================================
// Generic 3xTF32 mma conv building blocks (N=64 outputs, 256-pixel M block).
// smem float layout (dynamic): xh[256*36], xl[256*36], wh[64*36], wl[64*36],
// sum[64], sq[64]  (stats arrays optional per kernel)
// ============================================================================
#define SXH 0
#define SXL 9216
#define SWH 18432
#define SWL 20736
#define SST 23040
#define CONV_SMEM_F (23040 + 128)

// Stage one 32-wide K-chunk of weights (w is [64][K] row-major)
__device__ __forceinline__ void stage_w(float* cs, const float* __restrict__ w,
                                        int K, int k0, int tid) {
    for (int tt = tid; tt < 2048; tt += 256) {
        int oc = tt >> 5, cc = tt & 31;
        float wv = w[oc * K + k0 + cc];
        float hi = tf32r(wv);
        cs[SWH + oc * 36 + cc] = hi;
        cs[SWL + oc * 36 + cc] = tf32r(wv - hi);
    }
}

// Inner compute: accumulate 32-wide K chunk for this warp's 2 m16 tiles
__device__ __forceinline__ void conv_chunk(float* cs, float acc[2][8][4],
                                           int m0, int g, int t) {
#pragma unroll
    for (int kc = 0; kc < 32; kc += 8) {
        float ah[2][4], al[2][4];
#pragma unroll
        for (int tile = 0; tile < 2; tile++) {
            int r = m0 + tile * 16;
            ah[tile][0] = cs[SXH + (r + g) * 36 + kc + t];
            ah[tile][1] = cs[SXH + (r + g + 8) * 36 + kc + t];
            ah[tile][2] = cs[SXH + (r + g) * 36 + kc + t + 4];
            ah[tile][3] = cs[SXH + (r + g + 8) * 36 + kc + t + 4];
            al[tile][0] = cs[SXL + (r + g) * 36 + kc + t];
            al[tile][1] = cs[SXL + (r + g + 8) * 36 + kc + t];
            al[tile][2] = cs[SXL + (r + g) * 36 + kc + t + 4];
            al[tile][3] = cs[SXL + (r + g + 8) * 36 + kc + t + 4];
        }
#pragma unroll
        for (int nh = 0; nh < 2; nh++) {
            float bh[4][2], bl[4][2];
#pragma unroll
            for (int q = 0; q < 4; q++) {
                int n = (nh * 4 + q) * 8 + g;
                bh[q][0] = cs[SWH + n * 36 + kc + t];
                bh[q][1] = cs[SWH + n * 36 + kc + t + 4];
                bl[q][0] = cs[SWL + n * 36 + kc + t];
                bl[q][1] = cs[SWL + n * 36 + kc + t + 4];
            }
#pragma unroll
            for (int tile = 0; tile < 2; tile++)
#pragma unroll
                for (int q = 0; q < 4; q++) {
                    int nt = nh * 4 + q;
                    mma8(acc[tile][nt], ah[tile][0], ah[tile][1], ah[tile][2], ah[tile][3],
                         bh[q][0], bh[q][1]);
                    mma8(acc[tile][nt], al[tile][0], al[tile][1], al[tile][2], al[tile][3],
                         bh[q][0], bh[q][1]);
                    mma8(acc[tile][nt], ah[tile][0], ah[tile][1], ah[tile][2], ah[tile][3],
                         bl[q][0], bl[q][1]);
                }
        }
    }
}

// Stats: reduce acc over pixel rows into s_sum/s_sq (per output channel)
__device__ __forceinline__ void conv_stats(float* cs, float acc[2][8][4],
                                           int lane, int g, int t) {
#pragma unroll
    for (int nt = 0; nt < 8; nt++) {
        float v0 = acc[0][nt][0] + acc[0][nt][2] + acc[1][nt][0] + acc[1][nt][2];
        float v1 = acc[0][nt][1] + acc[0][nt][3] + acc[1][nt][1] + acc[1][nt][3];
        float q0 = acc[0][nt][0]*acc[0][nt][0] + acc[0][nt][2]*acc[0][nt][2]
                 + acc[1][nt][0]*acc[1][nt][0] + acc[1][nt][2]*acc[1][nt][2];
        float q1 = acc[0][nt][1]*acc[0][nt][1] + acc[0][nt][3]*acc[0][nt][3]
                 + acc[1][nt][1]*acc[1][nt][1] + acc[1][nt][3]*acc[1][nt][3];
#pragma unroll
        for (int off = 4; off < 32; off <<= 1) {
            v0 += __shfl_xor_sync(FULLM, v0, off);
            v1 += __shfl_xor_sync(FULLM, v1, off);
            q0 += __shfl_xor_sync(FULLM, q0, off);
            q1 += __shfl_xor_sync(FULLM, q1, off);
        }
        if (lane < 4) {
            int col = nt * 8 + 2 * t;
            atomicAdd(&cs[SST + col], v0);
            atomicAdd(&cs[SST + col + 1], v1);
            atomicAdd(&cs[SST + 64 + col], q0);
            atomicAdd(&cs[SST + 64 + col + 1], q1);
        }
    }
}

// ---------------- conv1 (K=256, x channel-major, transpose stage) -----------
__global__ void __launch_bounds__(256) k_conv1_mma(const float* __restrict__ x,
                                                   const float* __restrict__ w) {
    extern __shared__ float cs[];
    int tid = threadIdx.x, lane = tid & 31, wrp = tid >> 5;
    int g = lane >> 2, t = lane & 3;
    int p0 = blockIdx.x * 256;
    if (tid < 128) cs[SST + tid] = 0.f;
    float acc[2][8][4];
#pragma unroll
    for (int a = 0; a < 2; a++)
#pragma unroll
        for (int bb = 0; bb < 8; bb++)
#pragma unroll
            for (int c = 0; c < 4; c++) acc[a][bb][c] = 0.f;
    int m0 = wrp * 32;
    for (int k0 = 0; k0 < 256; k0 += 32) {
        __syncthreads();
        stage_w(cs, w, 256, k0, tid);
        for (int tt = tid; tt < 8192; tt += 256) {
            int cc = tt >> 8, p = tt & 255;
            int gp = p0 + p;
            float xv = (gp < HW) ? x[(size_t)(k0 + cc) * HW + gp] : 0.f;
            float hi = tf32r(xv);
            cs[SXH + p * 36 + cc] = hi;
            cs[SXL + p * 36 + cc] = tf32r(xv - hi);
        }
        __syncthreads();
        conv_chunk(cs, acc, m0, g, t);
    }
    // epilogue: store + stats
#pragma unroll
    for (int tile = 0; tile < 2; tile++) {
        int r0 = p0 + m0 + tile * 16 + g;
#pragma unroll
        for (int nt = 0; nt < 8; nt++) {
            int col = nt * 8 + 2 * t;
            if (r0 < HW)
                *(float2*)(g_y1 + (size_t)r0 * 64 + col) = make_float2(acc[tile][nt][0], acc[tile][nt][1]);
            if (r0 + 8 < HW)
                *(float2*)(g_y1 + (size_t)(r0 + 8) * 64 + col) = make_float2(acc[tile][nt][2], acc[tile][nt][3]);
        }
    }
    conv_stats(cs, acc, lane, g, t);
    __syncthreads();
    if (tid < 64) {
        atomicAdd(&g_stats[tid], cs[SST + tid]);
        atomicAdd(&g_stats[64 + tid], cs[SST + 64 + tid]);
    }
}

// ---------------- convwo (K=64, img pixel-major, bias+relu) -----------------
__global__ void __launch_bounds__(256) k_convwo_mma(const float* __restrict__ wo,
                                                    const float* __restrict__ bo) {
    extern __shared__ float cs[];
    int tid = threadIdx.x, lane = tid & 31, wrp = tid >> 5;
    int g = lane >> 2, t = lane & 3;
    int p0 = blockIdx.x * 256;
    if (tid < 64) cs[SST + tid] = bo[tid];
    float acc[2][8][4];
#pragma unroll
    for (int a = 0; a < 2; a++)
#pragma unroll
        for (int bb = 0; bb < 8; bb++)
#pragma unroll
            for (int c = 0; c < 4; c++) acc[a][bb][c] = 0.f;
    int m0 = wrp * 32;
    for (int k0 = 0; k0 < 64; k0 += 32) {
        __syncthreads();
        stage_w(cs, wo, 64, k0, tid);
        for (int tt = tid; tt < 8192; tt += 256) {
            int p = tt >> 5, cc = tt & 31;
            int gp = p0 + p;
            float xv = (gp < HW) ? g_img[(size_t)gp * 64 + k0 + cc] : 0.f;
            float hi = tf32r(xv);
            cs[SXH + p * 36 + cc] = hi;
            cs[SXL + p * 36 + cc] = tf32r(xv - hi);
        }
        __syncthreads();
        conv_chunk(cs, acc, m0, g, t);
    }
#pragma unroll
    for (int tile = 0; tile < 2; tile++) {
        int r0 = p0 + m0 + tile * 16 + g;
#pragma unroll
        for (int nt = 0; nt < 8; nt++) {
            int col = nt * 8 + 2 * t;
            float b0 = cs[SST + col], b1 = cs[SST + col + 1];
            if (r0 < HW)
                *(float2*)(g_xc + (size_t)r0 * 128 + col) =
                    make_float2(fmaxf(acc[tile][nt][0] + b0, 0.f), fmaxf(acc[tile][nt][1] + b1, 0.f));
            if (r0 + 8 < HW)
                *(float2*)(g_xc + (size_t)(r0 + 8) * 128 + col) =
                    make_float2(fmaxf(acc[tile][nt][2] + b0, 0.f), fmaxf(acc[tile][nt][3] + b1, 0.f));
        }
    }
}

// ---------------- conv2 (K=128, xc pixel-major, + BN2 stats) ----------------
__global__ void __launch_bounds__(256) k_conv2_mma(const float* __restrict__ w2) {
    extern __shared__ float cs[];
    int tid = threadIdx.x, lane = tid & 31, wrp = tid >> 5;
    int g = lane >> 2, t = lane & 3;
    int p0 = blockIdx.x * 256;
    if (tid < 128) cs[SST + tid] = 0.f;
    float acc[2][8][4];
#pragma unroll
    for (int a = 0; a < 2; a++)
#pragma unroll
        for (int bb = 0; bb < 8; bb++)
#pragma unroll
            for (int c = 0; c < 4; c++) acc[a][bb][c] = 0.f;
    int m0 = wrp * 32;
    for (int k0 = 0; k0 < 128; k0 += 32) {
        __syncthreads();
        stage_w(cs, w2, 128, k0, tid);
        for (int tt = tid; tt < 8192; tt += 256) {
            int p = tt >> 5, cc = tt & 31;
            int gp = p0 + p;
            float xv = (gp < HW) ? g_xc[(size_t)gp * 128 + k0 + cc] : 0.f;
            float hi = tf32r(xv);
            cs[SXH + p * 36 + cc] = hi;
            cs[SXL + p * 36 + cc] = tf32r(xv - hi);
        }
        __syncthreads();
        conv_chunk(cs, acc, m0, g, t);
    }
#pragma unroll
    for (int tile = 0; tile < 2; tile++) {
        int r0 = p0 + m0 + tile * 16 + g;
#pragma unroll
        for (int nt = 0; nt < 8; nt++) {
            int col = nt * 8 + 2 * t;
            if (r0 < HW)
                *(float2*)(g_y2 + (size_t)r0 * 64 + col) = make_float2(acc[tile][nt][0], acc[tile][nt][1]);
            if (r0 + 8 < HW)
                *(float2*)(g_y2 + (size_t)(r0 + 8) * 64 + col) = make_float2(acc[tile][nt][2], acc[tile][nt][3]);
        }
    }
    conv_stats(cs, acc, lane, g, t);
    __syncthreads();
    if (tid < 64) {
        atomicAdd(&g_stats[128 + tid], cs[SST + tid]);
        atomicAdd(&g_stats[192 + tid], cs[SST + 64 + tid]);
    }
}

// ---------------- BN finalize / apply ---------------------------------------
__global__ void k_fin(const float* __restrict__ g, const float* __restrict__ b, int which) {
    int c = threadIdx.x;
    if (c < 64) {
        const float inv = 1.f / (float)HW;
        float m   = g_stats[which * 128 + c] * inv;
        float var = g_stats[which * 128 + 64 + c] * inv - m * m;
        float rs  = rsqrtf(var + 1e-5f);
        float sc  = rs * g[c];
        g_bn[which * 128 + c]      = sc;
        g_bn[which * 128 + 64 + c] = b[c] - m * sc;
    }
}

__global__ void k_bnrelu1() {
    __shared__ float s_sc[64], s_sh[64];
    if (threadIdx.x < 64) {
        s_sc[threadIdx.x] = g_bn[threadIdx.x];
        s_sh[threadIdx.x] = g_bn[64 + threadIdx.x];
    }
    __syncthreads();
    int total = HW * 16;
    for (int idx = blockIdx.x * blockDim.x + threadIdx.x; idx < total;
         idx += gridDim.x * blockDim.x) {
        int p = idx >> 4, c4 = idx & 15;
        float4 v = ((const float4*)g_y1)[idx];
        int c = c4 * 4;
        v.x = fmaxf(fmaf(v.x, s_sc[c + 0], s_sh[c + 0]), 0.f);
        v.y = fmaxf(fmaf(v.y, s_sc[c + 1], s_sh[c + 1]), 0.f);
        v.z = fmaxf(fmaf(v.z, s_sc[c + 2], s_sh[c + 2]), 0.f);
        v.w = fmaxf(fmaf(v.w, s_sc[c + 3], s_sh[c + 3]), 0.f);
        ((float4*)g_xc)[p * 32 + 16 + c4] = v;
    }
}

// ---------------- fused attention: gather+proj+flash-mma+scatter ------------
#define WT_OFF   0
#define TOK_OFF  3104
#define SK_OFF   (3104 + 10944)
#define SV_OFF   (14048 + 11520)
#define SP_OFF   (25568 + 12800)
#define SPOS_OFF (38368 + 8704)
#define ATTN_SMEM_F (47072 + 304)

__global__ void __launch_bounds__(256) k_attn(const float* __restrict__ wq,
                                              const float* __restrict__ wkv,
                                              const int* __restrict__ obj_dict,
                                              const int* __restrict__ bg_dict,
                                              const int* __restrict__ rand_inds) {
    extern __shared__ float sm[];
    float* s_wT  = sm + WT_OFF;
    float* s_tok = sm + TOK_OFF;
    float* s_k   = sm + SK_OFF;
    float* s_v   = sm + SV_OFF;
    float* s_p   = sm + SP_OFF;
    int*   s_pos = (int*)(sm + SPOS_OFF);

    int b = blockIdx.x, h = b / 300, i = b % 300;
    int tid = threadIdx.x, lane = tid & 31, wrp = tid >> 5;
    int g = lane >> 2, t = lane & 3;

    for (int idx = tid; idx < 1024; idx += 256) {
        int o = idx >> 5, d = idx & 31;
        s_wT[d * 97 + o] = wq[idx];
    }
    for (int idx = tid; idx < 2048; idx += 256) {
        int o = idx >> 5, d = idx & 31;
        s_wT[d * 97 + 32 + o] = wkv[idx];
    }
    const int* __restrict__ dict = (i < 150) ? obj_dict : bg_dict;
    for (int j = tid; j < 300; j += 256)
        s_pos[j] = dict[rand_inds[(h * 300 + i) * 300 + j]];
    for (int idx = tid; idx < 4 * 36; idx += 256)  s_tok[300 * 36 + idx] = 0.f;
    for (int idx = tid; idx < 16 * 36; idx += 256) s_k[304 * 36 + idx]   = 0.f;
    for (int idx = tid; idx < 16 * 40; idx += 256) s_v[304 * 40 + idx]   = 0.f;
    __syncthreads();

    for (int tt = tid; tt < 9600; tt += 256) {
        int j = tt >> 5, d = tt & 31;
        s_tok[j * 36 + d] = g_xc[(size_t)s_pos[j] * 128 + 64 + h * 32 + d];
    }
    __syncthreads();

    const float qscale = 0.17677669529663687f;
    for (int j = wrp; j < 304; j += 8) {
        float aq = 0.f, ak = 0.f, av = 0.f;
#pragma unroll
        for (int d2 = 0; d2 < 32; d2++) {
            float tv = s_tok[j * 36 + d2];
            aq = fmaf(s_wT[d2 * 97 + lane], tv, aq);
            ak = fmaf(s_wT[d2 * 97 + 32 + lane], tv, ak);
            av = fmaf(s_wT[d2 * 97 + 64 + lane], tv, av);
        }
        s_k[j * 36 + lane] = tf32r(ak);
        s_v[j * 40 + lane] = tf32r(av);
        s_tok[j * 36 + lane] = tf32r(aq * qscale);
    }
    __syncthreads();

    float* pw = s_p + wrp * (16 * 68);
    for (int mt = wrp; mt < 19; mt += 8) {
        int m0 = mt * 16;
        float o[4][4];
#pragma unroll
        for (int a = 0; a < 4; a++)
#pragma unroll
            for (int bb = 0; bb < 4; bb++) o[a][bb] = 0.f;
        float mr0 = -1e30f, mr1 = -1e30f, l0 = 0.f, l1 = 0.f;

#pragma unroll 1
        for (int nc = 0; nc < 5; nc++) {
            int n0 = nc * 64;
            float csr[8][4];
#pragma unroll
            for (int nt = 0; nt < 8; nt++)
#pragma unroll
                for (int cc = 0; cc < 4; cc++) csr[nt][cc] = 0.f;
#pragma unroll
            for (int ks = 0; ks < 4; ks++) {
                int kc = ks * 8;
                float a0 = s_tok[(m0 + g) * 36 + kc + t];
                float a1 = s_tok[(m0 + g + 8) * 36 + kc + t];
                float a2 = s_tok[(m0 + g) * 36 + kc + t + 4];
                float a3 = s_tok[(m0 + g + 8) * 36 + kc + t + 4];
#pragma unroll
                for (int nt = 0; nt < 8; nt++) {
                    int nn = n0 + nt * 8 + g;
                    float b0 = s_k[nn * 36 + kc + t];
                    float b1 = s_k[nn * 36 + kc + t + 4];
                    mma8(csr[nt], a0, a1, a2, a3, b0, b1);
                }
            }
            if (nc == 4) {
#pragma unroll
                for (int nt = 0; nt < 8; nt++) {
                    int cg = 256 + nt * 8 + 2 * t;
                    if (cg >= 300)     { csr[nt][0] = -1e30f; csr[nt][2] = -1e30f; }
                    if (cg + 1 >= 300) { csr[nt][1] = -1e30f; csr[nt][3] = -1e30f; }
                }
            }
            float cm0 = -1e30f, cm1 = -1e30f;
#pragma unroll
            for (int nt = 0; nt < 8; nt++) {
                cm0 = fmaxf(cm0, fmaxf(csr[nt][0], csr[nt][1]));
                cm1 = fmaxf(cm1, fmaxf(csr[nt][2], csr[nt][3]));
            }
            cm0 = fmaxf(cm0, __shfl_xor_sync(FULLM, cm0, 1));
            cm0 = fmaxf(cm0, __shfl_xor_sync(FULLM, cm0, 2));
            cm1 = fmaxf(cm1, __shfl_xor_sync(FULLM, cm1, 1));
            cm1 = fmaxf(cm1, __shfl_xor_sync(FULLM, cm1, 2));
            float nm0 = fmaxf(mr0, cm0), nm1 = fmaxf(mr1, cm1);
            float f0 = __expf(mr0 - nm0), f1 = __expf(mr1 - nm1);
            mr0 = nm0; mr1 = nm1;
            float sum0 = 0.f, sum1 = 0.f;
#pragma unroll
            for (int nt = 0; nt < 8; nt++) {
                float p0 = __expf(csr[nt][0] - nm0);
                float p1 = __expf(csr[nt][1] - nm0);
                float p2 = __expf(csr[nt][2] - nm1);
                float p3 = __expf(csr[nt][3] - nm1);
                sum0 += p0 + p1; sum1 += p2 + p3;
                int pc = nt * 8 + 2 * t;
                pw[g * 68 + pc]           = tf32r(p0);
                pw[g * 68 + pc + 1]       = tf32r(p1);
                pw[(g + 8) * 68 + pc]     = tf32r(p2);
                pw[(g + 8) * 68 + pc + 1] = tf32r(p3);
            }
            sum0 += __shfl_xor_sync(FULLM, sum0, 1);
            sum0 += __shfl_xor_sync(FULLM, sum0, 2);
            sum1 += __shfl_xor_sync(FULLM, sum1, 1);
            sum1 += __shfl_xor_sync(FULLM, sum1, 2);
            l0 = l0 * f0 + sum0;
            l1 = l1 * f1 + sum1;
#pragma unroll
            for (int ot = 0; ot < 4; ot++) {
                o[ot][0] *= f0; o[ot][1] *= f0;
                o[ot][2] *= f1; o[ot][3] *= f1;
            }
            __syncwarp();
#pragma unroll
            for (int ks2 = 0; ks2 < 8; ks2++) {
                int kc = ks2 * 8;
                float a0 = pw[g * 68 + kc + t];
                float a1 = pw[(g + 8) * 68 + kc + t];
                float a2 = pw[g * 68 + kc + t + 4];
                float a3 = pw[(g + 8) * 68 + kc + t + 4];
                int kg = n0 + kc;
#pragma unroll
                for (int ot = 0; ot < 4; ot++) {
                    float b0 = s_v[(kg + t) * 40 + ot * 8 + g];
                    float b1 = s_v[(kg + t + 4) * 40 + ot * 8 + g];
                    mma8(o[ot], a0, a1, a2, a3, b0, b1);
                }
            }
            __syncwarp();
        }
        float i0 = __frcp_rn(l0), i1 = __frcp_rn(l1);
#pragma unroll
        for (int ot = 0; ot < 4; ot++) {
            int col = ot * 8 + 2 * t;
            s_tok[(m0 + g) * 36 + col]         = o[ot][0] * i0;
            s_tok[(m0 + g) * 36 + col + 1]     = o[ot][1] * i0;
            s_tok[(m0 + g + 8) * 36 + col]     = o[ot][2] * i1;
            s_tok[(m0 + g + 8) * 36 + col + 1] = o[ot][3] * i1;
        }
    }
    __syncthreads();

    for (int tt = tid; tt < 9600; tt += 256) {
        int c = tt >> 5, e = tt & 31;
        int idx = e * 300 + c;
        g_img[(size_t)s_pos[c] * 64 + h * 32 + e] = s_tok[(idx >> 5) * 36 + (idx & 31)];
    }
}

// ---------------- BN2 + relu + transpose to output --------------------------
__global__ void __launch_bounds__(256) k_out(float* __restrict__ out) {
    __shared__ float s[64 * 65];
    __shared__ float s_sc[64], s_sh[64];
    int tid = threadIdx.x;
    if (tid < 64) { s_sc[tid] = g_bn[128 + tid]; s_sh[tid] = g_bn[192 + tid]; }
    int p0 = blockIdx.x * 64;
    for (int t = tid; t < 4096; t += 256) {
        int pl = t >> 6, c = t & 63;
        int p = p0 + pl;
        s[pl * 65 + c] = (p < HW) ? g_y2[(size_t)p * 64 + c] : 0.f;
    }
    __syncthreads();
    for (int t = tid; t < 4096; t += 256) {
        int c = t >> 6, pl = t & 63;
        int p = p0 + pl;
        if (p < HW)
            out[(size_t)c * HW + p] = fmaxf(fmaf(s[pl * 65 + c], s_sc[c], s_sh[c]), 0.f);
    }
}

// ---------------- launch -----------------------------------------------------
extern "C" void kernel_launch(void* const* d_in, const int* in_sizes, int n_in,
                              void* d_out, int out_size) {
    const float* x   = (const float*)d_in[0];
    const float* w1  = (const float*)d_in[1];
    const float* g1  = (const float*)d_in[2];
    const float* b1  = (const float*)d_in[3];
    const float* wq  = (const float*)d_in[4];
    const float* wkv = (const float*)d_in[5];
    const float* wo  = (const float*)d_in[6];
    const float* bo  = (const float*)d_in[7];
    const float* w2  = (const float*)d_in[8];
    const float* g2  = (const float*)d_in[9];
    const float* b2  = (const float*)d_in[10];
    const int* objd  = (const int*)d_in[11];
    const int* bgd   = (const int*)d_in[12];
    const int* ri    = (const int*)d_in[13];
    float* out = (float*)d_out;

    int conv_smem = CONV_SMEM_F * sizeof(float);
    cudaFuncSetAttribute(k_conv1_mma,  cudaFuncAttributeMaxDynamicSharedMemorySize, conv_smem);
    cudaFuncSetAttribute(k_convwo_mma, cudaFuncAttributeMaxDynamicSharedMemorySize, conv_smem);
    cudaFuncSetAttribute(k_conv2_mma,  cudaFuncAttributeMaxDynamicSharedMemorySize, conv_smem);

    int nblk = (HW + 255) / 256;   // 352

    k_zero<<<1, 256>>>();
    k_conv1_mma<<<nblk, 256, conv_smem>>>(x, w1);
    k_fin<<<1, 64>>>(g1, b1, 0);
    k_bnrelu1<<<1024, 256>>>();

    size_t attn_smem = (size_t)ATTN_SMEM_F * sizeof(float);
    cudaFuncSetAttribute(k_attn, cudaFuncAttributeMaxDynamicSharedMemorySize, (int)attn_smem);
    k_attn<<<600, 256, attn_smem>>>(wq, wkv, objd, bgd, ri);

    k_convwo_mma<<<nblk, 256, conv_smem>>>(wo, bo);
    k_conv2_mma<<<nblk, 256, conv_smem>>>(w2);
    k_fin<<<1, 64>>>(g2, b2, 1);
    k_out<<<(HW + 63) / 64, 256>>>(out);
}

// round 16
// speedup vs baseline: 2.4116x; 1.0333x over previous
#include <cuda_runtime.h>
#include <cstdint>

#define HW 90000
#define FULLM 0xffffffffu

// ---------------- tf32 helpers ----------------------------------------------
__device__ __forceinline__ float tf32r(float x) {
    uint32_t u; asm("cvt.rna.tf32.f32 %0, %1;" : "=r"(u) : "f"(x));
    return __uint_as_float(u);
}
__device__ __forceinline__ void mma8(float c[4], float a0, float a1, float a2, float a3,
                                     float b0, float b1) {
    asm volatile("mma.sync.aligned.m16n8k8.row.col.f32.tf32.tf32.f32 "
        "{%0,%1,%2,%3}, {%4,%5,%6,%7}, {%8,%9}, {%0,%1,%2,%3};"
        : "+f"(c[0]), "+f"(c[1]), "+f"(c[2]), "+f"(c[3])
        : "r"(__float_as_uint(a0)), "r"(__float_as_uint(a1)),
          "r"(__float_as_uint(a2)), "r"(__float_as_uint(a3)),
          "r"(__float_as_uint(b0)), "r"(__float_as_uint(b1)));
}

// ---------------- scratch ----------------------------------------------------
__device__ float g_y1[HW * 64];      // conv1 raw (pre-BN), pixel-major
__device__ float g_xa[HW * 64];      // attn branch after wo-conv (pixel-major)
__device__ float g_img[HW * 64];     // attention scattered image
__device__ float g_y2[HW * 64];      // conv2 raw
__device__ float g_stats[256];
__device__ float g_bn[256];

__global__ void k_zero() { g_stats[threadIdx.x] = 0.f; }

// ============================================================================
// 3xTF32 mma conv building blocks (N=64 outputs, 256-pixel M block)
// ============================================================================
#define SXH 0
#define SXL 9216
#define SWH 18432
#define SWL 20736
#define SST 23040
#define SBN2 23168
#define CONV_SMEM_F (23168 + 128)

__device__ __forceinline__ void stage_w(float* cs, const float* __restrict__ w,
                                        int K, int k0, int tid) {
    for (int tt = tid; tt < 2048; tt += 256) {
        int oc = tt >> 5, cc = tt & 31;
        float wv = w[oc * K + k0 + cc];
        float hi = tf32r(wv);
        cs[SWH + oc * 36 + cc] = hi;
        cs[SWL + oc * 36 + cc] = tf32r(wv - hi);
    }
}

__device__ __forceinline__ void conv_chunk(float* cs, float acc[2][8][4],
                                           int m0, int g, int t) {
#pragma unroll
    for (int kc = 0; kc < 32; kc += 8) {
        float ah[2][4], al[2][4];
#pragma unroll
        for (int tile = 0; tile < 2; tile++) {
            int r = m0 + tile * 16;
            ah[tile][0] = cs[SXH + (r + g) * 36 + kc + t];
            ah[tile][1] = cs[SXH + (r + g + 8) * 36 + kc + t];
            ah[tile][2] = cs[SXH + (r + g) * 36 + kc + t + 4];
            ah[tile][3] = cs[SXH + (r + g + 8) * 36 + kc + t + 4];
            al[tile][0] = cs[SXL + (r + g) * 36 + kc + t];
            al[tile][1] = cs[SXL + (r + g + 8) * 36 + kc + t];
            al[tile][2] = cs[SXL + (r + g) * 36 + kc + t + 4];
            al[tile][3] = cs[SXL + (r + g + 8) * 36 + kc + t + 4];
        }
#pragma unroll
        for (int nh = 0; nh < 2; nh++) {
            float bh[4][2], bl[4][2];
#pragma unroll
            for (int q = 0; q < 4; q++) {
                int n = (nh * 4 + q) * 8 + g;
                bh[q][0] = cs[SWH + n * 36 + kc + t];
                bh[q][1] = cs[SWH + n * 36 + kc + t + 4];
                bl[q][0] = cs[SWL + n * 36 + kc + t];
                bl[q][1] = cs[SWL + n * 36 + kc + t + 4];
            }
#pragma unroll
            for (int tile = 0; tile < 2; tile++)
#pragma unroll
                for (int q = 0; q < 4; q++) {
                    int nt = nh * 4 + q;
                    mma8(acc[tile][nt], ah[tile][0], ah[tile][1], ah[tile][2], ah[tile][3],
                         bh[q][0], bh[q][1]);
                    mma8(acc[tile][nt], al[tile][0], al[tile][1], al[tile][2], al[tile][3],
                         bh[q][0], bh[q][1]);
                    mma8(acc[tile][nt], ah[tile][0], ah[tile][1], ah[tile][2], ah[tile][3],
                         bl[q][0], bl[q][1]);
                }
        }
    }
}

__device__ __forceinline__ void conv_stats(float* cs, float acc[2][8][4],
                                           int lane, int g, int t) {
#pragma unroll
    for (int nt = 0; nt < 8; nt++) {
        float v0 = acc[0][nt][0] + acc[0][nt][2] + acc[1][nt][0] + acc[1][nt][2];
        float v1 = acc[0][nt][1] + acc[0][nt][3] + acc[1][nt][1] + acc[1][nt][3];
        float q0 = acc[0][nt][0]*acc[0][nt][0] + acc[0][nt][2]*acc[0][nt][2]
                 + acc[1][nt][0]*acc[1][nt][0] + acc[1][nt][2]*acc[1][nt][2];
        float q1 = acc[0][nt][1]*acc[0][nt][1] + acc[0][nt][3]*acc[0][nt][3]
                 + acc[1][nt][1]*acc[1][nt][1] + acc[1][nt][3]*acc[1][nt][3];
#pragma unroll
        for (int off = 4; off < 32; off <<= 1) {
            v0 += __shfl_xor_sync(FULLM, v0, off);
            v1 += __shfl_xor_sync(FULLM, v1, off);
            q0 += __shfl_xor_sync(FULLM, q0, off);
            q1 += __shfl_xor_sync(FULLM, q1, off);
        }
        if (lane < 4) {
            int col = nt * 8 + 2 * t;
            atomicAdd(&cs[SST + col], v0);
            atomicAdd(&cs[SST + col + 1], v1);
            atomicAdd(&cs[SST + 64 + col], q0);
            atomicAdd(&cs[SST + 64 + col + 1], q1);
        }
    }
}

// ---------------- conv1 (K=256, x channel-major) ----------------------------
__global__ void __launch_bounds__(256) k_conv1_mma(const float* __restrict__ x,
                                                   const float* __restrict__ w) {
    extern __shared__ float cs[];
    int tid = threadIdx.x, lane = tid & 31, wrp = tid >> 5;
    int g = lane >> 2, t = lane & 3;
    int p0 = blockIdx.x * 256;
    if (tid < 128) cs[SST + tid] = 0.f;
    float acc[2][8][4];
#pragma unroll
    for (int a = 0; a < 2; a++)
#pragma unroll
        for (int bb = 0; bb < 8; bb++)
#pragma unroll
            for (int c = 0; c < 4; c++) acc[a][bb][c] = 0.f;
    int m0 = wrp * 32;
    for (int k0 = 0; k0 < 256; k0 += 32) {
        __syncthreads();
        stage_w(cs, w, 256, k0, tid);
        for (int tt = tid; tt < 8192; tt += 256) {
            int cc = tt >> 8, p = tt & 255;
            int gp = p0 + p;
            float xv = (gp < HW) ? x[(size_t)(k0 + cc) * HW + gp] : 0.f;
            float hi = tf32r(xv);
            cs[SXH + p * 36 + cc] = hi;
            cs[SXL + p * 36 + cc] = tf32r(xv - hi);
        }
        __syncthreads();
        conv_chunk(cs, acc, m0, g, t);
    }
#pragma unroll
    for (int tile = 0; tile < 2; tile++) {
        int r0 = p0 + m0 + tile * 16 + g;
#pragma unroll
        for (int nt = 0; nt < 8; nt++) {
            int col = nt * 8 + 2 * t;
            if (r0 < HW)
                *(float2*)(g_y1 + (size_t)r0 * 64 + col) = make_float2(acc[tile][nt][0], acc[tile][nt][1]);
            if (r0 + 8 < HW)
                *(float2*)(g_y1 + (size_t)(r0 + 8) * 64 + col) = make_float2(acc[tile][nt][2], acc[tile][nt][3]);
        }
    }
    conv_stats(cs, acc, lane, g, t);
    __syncthreads();
    if (tid < 64) {
        atomicAdd(&g_stats[tid], cs[SST + tid]);
        atomicAdd(&g_stats[64 + tid], cs[SST + 64 + tid]);
    }
}

// ---------------- convwo (K=64, img pixel-major, bias+relu -> g_xa) ---------
__global__ void __launch_bounds__(256) k_convwo_mma(const float* __restrict__ wo,
                                                    const float* __restrict__ bo) {
    extern __shared__ float cs[];
    int tid = threadIdx.x, lane = tid & 31, wrp = tid >> 5;
    int g = lane >> 2, t = lane & 3;
    int p0 = blockIdx.x * 256;
    if (tid < 64) cs[SST + tid] = bo[tid];
    float acc[2][8][4];
#pragma unroll
    for (int a = 0; a < 2; a++)
#pragma unroll
        for (int bb = 0; bb < 8; bb++)
#pragma unroll
            for (int c = 0; c < 4; c++) acc[a][bb][c] = 0.f;
    int m0 = wrp * 32;
    for (int k0 = 0; k0 < 64; k0 += 32) {
        __syncthreads();
        stage_w(cs, wo, 64, k0, tid);
        for (int tt = tid; tt < 8192; tt += 256) {
            int p = tt >> 5, cc = tt & 31;
            int gp = p0 + p;
            float xv = (gp < HW) ? g_img[(size_t)gp * 64 + k0 + cc] : 0.f;
            float hi = tf32r(xv);
            cs[SXH + p * 36 + cc] = hi;
            cs[SXL + p * 36 + cc] = tf32r(xv - hi);
        }
        __syncthreads();
        conv_chunk(cs, acc, m0, g, t);
    }
#pragma unroll
    for (int tile = 0; tile < 2; tile++) {
        int r0 = p0 + m0 + tile * 16 + g;
#pragma unroll
        for (int nt = 0; nt < 8; nt++) {
            int col = nt * 8 + 2 * t;
            float b0 = cs[SST + col], b1 = cs[SST + col + 1];
            if (r0 < HW)
                *(float2*)(g_xa + (size_t)r0 * 64 + col) =
                    make_float2(fmaxf(acc[tile][nt][0] + b0, 0.f), fmaxf(acc[tile][nt][1] + b1, 0.f));
            if (r0 + 8 < HW)
                *(float2*)(g_xa + (size_t)(r0 + 8) * 64 + col) =
                    make_float2(fmaxf(acc[tile][nt][2] + b0, 0.f), fmaxf(acc[tile][nt][3] + b1, 0.f));
        }
    }
}

// ---------------- conv2 (K=128: [xa ; bn1relu(y1)]) + BN2 stats -------------
__global__ void __launch_bounds__(256) k_conv2_mma(const float* __restrict__ w2) {
    extern __shared__ float cs[];
    int tid = threadIdx.x, lane = tid & 31, wrp = tid >> 5;
    int g = lane >> 2, t = lane & 3;
    int p0 = blockIdx.x * 256;
    if (tid < 128) cs[SST + tid] = 0.f;
    if (tid < 128) cs[SBN2 + tid] = g_bn[tid];   // sc[64], sh[64] for BN1
    float acc[2][8][4];
#pragma unroll
    for (int a = 0; a < 2; a++)
#pragma unroll
        for (int bb = 0; bb < 8; bb++)
#pragma unroll
            for (int c = 0; c < 4; c++) acc[a][bb][c] = 0.f;
    int m0 = wrp * 32;
    for (int k0 = 0; k0 < 128; k0 += 32) {
        __syncthreads();
        stage_w(cs, w2, 128, k0, tid);
        if (k0 < 64) {
            for (int tt = tid; tt < 8192; tt += 256) {
                int p = tt >> 5, cc = tt & 31;
                int gp = p0 + p;
                float xv = (gp < HW) ? g_xa[(size_t)gp * 64 + k0 + cc] : 0.f;
                float hi = tf32r(xv);
                cs[SXH + p * 36 + cc] = hi;
                cs[SXL + p * 36 + cc] = tf32r(xv - hi);
            }
        } else {
            for (int tt = tid; tt < 8192; tt += 256) {
                int p = tt >> 5, cc = tt & 31;
                int gp = p0 + p;
                int ch = k0 - 64 + cc;
                float xv = 0.f;
                if (gp < HW) {
                    float y = g_y1[(size_t)gp * 64 + ch];
                    xv = fmaxf(fmaf(y, cs[SBN2 + ch], cs[SBN2 + 64 + ch]), 0.f);
                }
                float hi = tf32r(xv);
                cs[SXH + p * 36 + cc] = hi;
                cs[SXL + p * 36 + cc] = tf32r(xv - hi);
            }
        }
        __syncthreads();
        conv_chunk(cs, acc, m0, g, t);
    }
#pragma unroll
    for (int tile = 0; tile < 2; tile++) {
        int r0 = p0 + m0 + tile * 16 + g;
#pragma unroll
        for (int nt = 0; nt < 8; nt++) {
            int col = nt * 8 + 2 * t;
            if (r0 < HW)
                *(float2*)(g_y2 + (size_t)r0 * 64 + col) = make_float2(acc[tile][nt][0], acc[tile][nt][1]);
            if (r0 + 8 < HW)
                *(float2*)(g_y2 + (size_t)(r0 + 8) * 64 + col) = make_float2(acc[tile][nt][2], acc[tile][nt][3]);
        }
    }
    conv_stats(cs, acc, lane, g, t);
    __syncthreads();
    if (tid < 64) {
        atomicAdd(&g_stats[128 + tid], cs[SST + tid]);
        atomicAdd(&g_stats[192 + tid], cs[SST + 64 + tid]);
    }
}

// ---------------- BN finalize ------------------------------------------------
__global__ void k_fin(const float* __restrict__ g, const float* __restrict__ b, int which) {
    int c = threadIdx.x;
    if (c < 64) {
        const float inv = 1.f / (float)HW;
        float m   = g_stats[which * 128 + c] * inv;
        float var = g_stats[which * 128 + 64 + c] * inv - m * m;
        float rs  = rsqrtf(var + 1e-5f);
        float sc  = rs * g[c];
        g_bn[which * 128 + c]      = sc;
        g_bn[which * 128 + 64 + c] = b[c] - m * sc;
    }
}

// ---------------- fused attention (BN1+relu gather, mma proj, flash, scatter)
#define W_OFF    0                      // 96 x 36  (wq scaled rows 0..31, wk 32..63, wv 64..95)
#define TOK_OFF  3456                   // 304 x 36 (tok -> Q -> O)
#define SK_OFF   (3456 + 10944)         // 320 x 36
#define SV_OFF   (14400 + 11520)        // 320 x 40
#define SP_OFF   (25920 + 12800)        // 8 x 16 x 68
#define SPOS_OFF (38720 + 8704)         // 304 ints
#define SBN_OFF  (47424 + 304)          // 64 floats (sc 0..31, sh 32..63)
#define ATTN_SMEM_F (47728 + 64)

__global__ void __launch_bounds__(256) k_attn(const float* __restrict__ wq,
                                              const float* __restrict__ wkv,
                                              const int* __restrict__ obj_dict,
                                              const int* __restrict__ bg_dict,
                                              const int* __restrict__ rand_inds) {
    extern __shared__ float sm[];
    float* s_w   = sm + W_OFF;
    float* s_tok = sm + TOK_OFF;
    float* s_k   = sm + SK_OFF;
    float* s_v   = sm + SV_OFF;
    float* s_p   = sm + SP_OFF;
    int*   s_pos = (int*)(sm + SPOS_OFF);
    float* s_bn  = sm + SBN_OFF;

    int b = blockIdx.x, h = b / 300, i = b % 300;
    int tid = threadIdx.x, lane = tid & 31, wrp = tid >> 5;
    int g = lane >> 2, t = lane & 3;

    const float qscale = 0.17677669529663687f;
    // stage weights [o][d], qscale folded into wq rows
    for (int idx = tid; idx < 1024; idx += 256) {
        int o = idx >> 5, d = idx & 31;
        s_w[o * 36 + d] = tf32r(wq[idx] * qscale);
    }
    for (int idx = tid; idx < 2048; idx += 256) {
        int o = idx >> 5, d = idx & 31;
        s_w[(32 + o) * 36 + d] = tf32r(wkv[idx]);
    }
    if (tid < 64) s_bn[tid] = g_bn[(tid & 31) + h * 32 + (tid >> 5) * 64];
    const int* __restrict__ dict = (i < 150) ? obj_dict : bg_dict;
    for (int j = tid; j < 300; j += 256)
        s_pos[j] = dict[rand_inds[(h * 300 + i) * 300 + j]];
    for (int idx = tid; idx < 4 * 36; idx += 256)  s_tok[300 * 36 + idx] = 0.f;
    for (int idx = tid; idx < 16 * 36; idx += 256) s_k[304 * 36 + idx]   = 0.f;
    for (int idx = tid; idx < 16 * 40; idx += 256) s_v[304 * 40 + idx]   = 0.f;
    __syncthreads();

    // gather tokens with BN1 + relu applied, tf32-rounded
    for (int tt = tid; tt < 9600; tt += 256) {
        int j = tt >> 5, d = tt & 31;
        float y = g_y1[(size_t)s_pos[j] * 64 + h * 32 + d];
        s_tok[j * 36 + d] = tf32r(fmaxf(fmaf(y, s_bn[d], s_bn[32 + d]), 0.f));
    }
    __syncthreads();

    // QKV projection via mma: out[304 x 96] = tok[304 x 32] @ w^T
    for (int mt = wrp; mt < 19; mt += 8) {
        int m0 = mt * 16;
        float acc[12][4];
#pragma unroll
        for (int nt = 0; nt < 12; nt++)
#pragma unroll
            for (int c = 0; c < 4; c++) acc[nt][c] = 0.f;
#pragma unroll
        for (int ks = 0; ks < 4; ks++) {
            int kc = ks * 8;
            float a0 = s_tok[(m0 + g) * 36 + kc + t];
            float a1 = s_tok[(m0 + g + 8) * 36 + kc + t];
            float a2 = s_tok[(m0 + g) * 36 + kc + t + 4];
            float a3 = s_tok[(m0 + g + 8) * 36 + kc + t + 4];
#pragma unroll
            for (int nt = 0; nt < 12; nt++) {
                float b0 = s_w[(nt * 8 + g) * 36 + kc + t];
                float b1 = s_w[(nt * 8 + g) * 36 + kc + t + 4];
                mma8(acc[nt], a0, a1, a2, a3, b0, b1);
            }
        }
        // epilogue: Q (nt 0..3) into own tok rows, K (4..7), V (8..11)
#pragma unroll
        for (int nt = 0; nt < 4; nt++) {
            int col = nt * 8 + 2 * t;
            s_tok[(m0 + g) * 36 + col]         = tf32r(acc[nt][0]);
            s_tok[(m0 + g) * 36 + col + 1]     = tf32r(acc[nt][1]);
            s_tok[(m0 + g + 8) * 36 + col]     = tf32r(acc[nt][2]);
            s_tok[(m0 + g + 8) * 36 + col + 1] = tf32r(acc[nt][3]);
        }
#pragma unroll
        for (int nt = 4; nt < 8; nt++) {
            int col = (nt - 4) * 8 + 2 * t;
            s_k[(m0 + g) * 36 + col]         = tf32r(acc[nt][0]);
            s_k[(m0 + g) * 36 + col + 1]     = tf32r(acc[nt][1]);
            s_k[(m0 + g + 8) * 36 + col]     = tf32r(acc[nt][2]);
            s_k[(m0 + g + 8) * 36 + col + 1] = tf32r(acc[nt][3]);
        }
#pragma unroll
        for (int nt = 8; nt < 12; nt++) {
            int col = (nt - 8) * 8 + 2 * t;
            s_v[(m0 + g) * 40 + col]         = tf32r(acc[nt][0]);
            s_v[(m0 + g) * 40 + col + 1]     = tf32r(acc[nt][1]);
            s_v[(m0 + g + 8) * 40 + col]     = tf32r(acc[nt][2]);
            s_v[(m0 + g + 8) * 40 + col + 1] = tf32r(acc[nt][3]);
        }
    }
    __syncthreads();

    // flash attention over 5 chunks of 64 cols
    float* pw = s_p + wrp * (16 * 68);
    for (int mt = wrp; mt < 19; mt += 8) {
        int m0 = mt * 16;
        float o[4][4];
#pragma unroll
        for (int a = 0; a < 4; a++)
#pragma unroll
            for (int bb = 0; bb < 4; bb++) o[a][bb] = 0.f;
        float mr0 = -1e30f, mr1 = -1e30f, l0 = 0.f, l1 = 0.f;

#pragma unroll 1
        for (int nc = 0; nc < 5; nc++) {
            int n0 = nc * 64;
            float csr[8][4];
#pragma unroll
            for (int nt = 0; nt < 8; nt++)
#pragma unroll
                for (int cc = 0; cc < 4; cc++) csr[nt][cc] = 0.f;
#pragma unroll
            for (int ks = 0; ks < 4; ks++) {
                int kc = ks * 8;
                float a0 = s_tok[(m0 + g) * 36 + kc + t];
                float a1 = s_tok[(m0 + g + 8) * 36 + kc + t];
                float a2 = s_tok[(m0 + g) * 36 + kc + t + 4];
                float a3 = s_tok[(m0 + g + 8) * 36 + kc + t + 4];
#pragma unroll
                for (int nt = 0; nt < 8; nt++) {
                    int nn = n0 + nt * 8 + g;
                    float b0 = s_k[nn * 36 + kc + t];
                    float b1 = s_k[nn * 36 + kc + t + 4];
                    mma8(csr[nt], a0, a1, a2, a3, b0, b1);
                }
            }
            if (nc == 4) {
#pragma unroll
                for (int nt = 0; nt < 8; nt++) {
                    int cg = 256 + nt * 8 + 2 * t;
                    if (cg >= 300)     { csr[nt][0] = -1e30f; csr[nt][2] = -1e30f; }
                    if (cg + 1 >= 300) { csr[nt][1] = -1e30f; csr[nt][3] = -1e30f; }
                }
            }
            float cm0 = -1e30f, cm1 = -1e30f;
#pragma unroll
            for (int nt = 0; nt < 8; nt++) {
                cm0 = fmaxf(cm0, fmaxf(csr[nt][0], csr[nt][1]));
                cm1 = fmaxf(cm1, fmaxf(csr[nt][2], csr[nt][3]));
            }
            cm0 = fmaxf(cm0, __shfl_xor_sync(FULLM, cm0, 1));
            cm0 = fmaxf(cm0, __shfl_xor_sync(FULLM, cm0, 2));
            cm1 = fmaxf(cm1, __shfl_xor_sync(FULLM, cm1, 1));
            cm1 = fmaxf(cm1, __shfl_xor_sync(FULLM, cm1, 2));
            float nm0 = fmaxf(mr0, cm0), nm1 = fmaxf(mr1, cm1);
            float f0 = __expf(mr0 - nm0), f1 = __expf(mr1 - nm1);
            mr0 = nm0; mr1 = nm1;
            float sum0 = 0.f, sum1 = 0.f;
#pragma unroll
            for (int nt = 0; nt < 8; nt++) {
                float p0 = __expf(csr[nt][0] - nm0);
                float p1 = __expf(csr[nt][1] - nm0);
                float p2 = __expf(csr[nt][2] - nm1);
                float p3 = __expf(csr[nt][3] - nm1);
                sum0 += p0 + p1; sum1 += p2 + p3;
                int pc = nt * 8 + 2 * t;
                pw[g * 68 + pc]           = tf32r(p0);
                pw[g * 68 + pc + 1]       = tf32r(p1);
                pw[(g + 8) * 68 + pc]     = tf32r(p2);
                pw[(g + 8) * 68 + pc + 1] = tf32r(p3);
            }
            sum0 += __shfl_xor_sync(FULLM, sum0, 1);
            sum0 += __shfl_xor_sync(FULLM, sum0, 2);
            sum1 += __shfl_xor_sync(FULLM, sum1, 1);
            sum1 += __shfl_xor_sync(FULLM, sum1, 2);
            l0 = l0 * f0 + sum0;
            l1 = l1 * f1 + sum1;
#pragma unroll
            for (int ot = 0; ot < 4; ot++) {
                o[ot][0] *= f0; o[ot][1] *= f0;
                o[ot][2] *= f1; o[ot][3] *= f1;
            }
            __syncwarp();
#pragma unroll
            for (int ks2 = 0; ks2 < 8; ks2++) {
                int kc = ks2 * 8;
                float a0 = pw[g * 68 + kc + t];
                float a1 = pw[(g + 8) * 68 + kc + t];
                float a2 = pw[g * 68 + kc + t + 4];
                float a3 = pw[(g + 8) * 68 + kc + t + 4];
                int kg = n0 + kc;
#pragma unroll
                for (int ot = 0; ot < 4; ot++) {
                    float b0 = s_v[(kg + t) * 40 + ot * 8 + g];
                    float b1 = s_v[(kg + t + 4) * 40 + ot * 8 + g];
                    mma8(o[ot], a0, a1, a2, a3, b0, b1);
                }
            }
            __syncwarp();
        }
        float i0 = __frcp_rn(l0), i1 = __frcp_rn(l1);
#pragma unroll
        for (int ot = 0; ot < 4; ot++) {
            int col = ot * 8 + 2 * t;
            s_tok[(m0 + g) * 36 + col]         = o[ot][0] * i0;
            s_tok[(m0 + g) * 36 + col + 1]     = o[ot][1] * i0;
            s_tok[(m0 + g + 8) * 36 + col]     = o[ot][2] * i1;
            s_tok[(m0 + g + 8) * 36 + col + 1] = o[ot][3] * i1;
        }
    }
    __syncthreads();

    // scatter with (j,d)->(e,c) reshape
    for (int tt = tid; tt < 9600; tt += 256) {
        int c = tt >> 5, e = tt & 31;
        int idx = e * 300 + c;
        g_img[(size_t)s_pos[c] * 64 + h * 32 + e] = s_tok[(idx >> 5) * 36 + (idx & 31)];
    }
}

// ---------------- BN2 + relu + transpose to output --------------------------
__global__ void __launch_bounds__(256) k_out(float* __restrict__ out) {
    __shared__ float s[64 * 65];
    __shared__ float s_sc[64], s_sh[64];
    int tid = threadIdx.x;
    if (tid < 64) { s_sc[tid] = g_bn[128 + tid]; s_sh[tid] = g_bn[192 + tid]; }
    int p0 = blockIdx.x * 64;
    for (int t = tid; t < 4096; t += 256) {
        int pl = t >> 6, c = t & 63;
        int p = p0 + pl;
        s[pl * 65 + c] = (p < HW) ? g_y2[(size_t)p * 64 + c] : 0.f;
    }
    __syncthreads();
    for (int t = tid; t < 4096; t += 256) {
        int c = t >> 6, pl = t & 63;
        int p = p0 + pl;
        if (p < HW)
            out[(size_t)c * HW + p] = fmaxf(fmaf(s[pl * 65 + c], s_sc[c], s_sh[c]), 0.f);
    }
}

// ---------------- launch -----------------------------------------------------
extern "C" void kernel_launch(void* const* d_in, const int* in_sizes, int n_in,
                              void* d_out, int out_size) {
    const float* x   = (const float*)d_in[0];
    const float* w1  = (const float*)d_in[1];
    const float* g1  = (const float*)d_in[2];
    const float* b1  = (const float*)d_in[3];
    const float* wq  = (const float*)d_in[4];
    const float* wkv = (const float*)d_in[5];
    const float* wo  = (const float*)d_in[6];
    const float* bo  = (const float*)d_in[7];
    const float* w2  = (const float*)d_in[8];
    const float* g2  = (const float*)d_in[9];
    const float* b2  = (const float*)d_in[10];
    const int* objd  = (const int*)d_in[11];
    const int* bgd   = (const int*)d_in[12];
    const int* ri    = (const int*)d_in[13];
    float* out = (float*)d_out;

    int conv_smem = CONV_SMEM_F * sizeof(float);
    cudaFuncSetAttribute(k_conv1_mma,  cudaFuncAttributeMaxDynamicSharedMemorySize, conv_smem);
    cudaFuncSetAttribute(k_convwo_mma, cudaFuncAttributeMaxDynamicSharedMemorySize, conv_smem);
    cudaFuncSetAttribute(k_conv2_mma,  cudaFuncAttributeMaxDynamicSharedMemorySize, conv_smem);

    int nblk = (HW + 255) / 256;   // 352

    k_zero<<<1, 256>>>();
    k_conv1_mma<<<nblk, 256, conv_smem>>>(x, w1);
    k_fin<<<1, 64>>>(g1, b1, 0);

    size_t attn_smem = (size_t)ATTN_SMEM_F * sizeof(float);
    cudaFuncSetAttribute(k_attn, cudaFuncAttributeMaxDynamicSharedMemorySize, (int)attn_smem);
    k_attn<<<600, 256, attn_smem>>>(wq, wkv, objd, bgd, ri);

    k_convwo_mma<<<nblk, 256, conv_smem>>>(wo, bo);
    k_conv2_mma<<<nblk, 256, conv_smem>>>(w2);
    k_fin<<<1, 64>>>(g2, b2, 1);
    k_out<<<(HW + 63) / 64, 256>>>(out);
}